// round 2
// baseline (speedup 1.0000x reference)
#include <cuda_runtime.h>
#include <math.h>

// ---------------------------------------------------------------------------
// ConvLSTM stack: 4x (ConvLSTM2D(valid input conv, same recurrent conv,
// hard_sigmoid gates i,f,c,o, tanh) + MaxPool(2,2,'SAME')) -> Dense(50) -> softmax
// B=32, T=24. All fp32.
// ---------------------------------------------------------------------------

static constexpr int Bv = 32;
static constexpr int Tv = 24;

// Layer dims
// L1: in 128x128x3  -> h 126x126xF4  -> pool 63x63
// L2: in 63x63x4    -> h 61x61xF8    -> pool 31x31
// L3: in 31x31x8    -> h 29x29xF12   -> pool 15x15
// L4: in 15x15x12   -> h 13x13xF16   -> pool 7x7
__device__ float g_hs1[(size_t)Bv*Tv*126*126*4];
__device__ float g_c1 [(size_t)Bv*126*126*4];
__device__ float g_p1 [(size_t)Bv*Tv*63*63*4];
__device__ float g_hs2[(size_t)Bv*Tv*61*61*8];
__device__ float g_c2 [(size_t)Bv*61*61*8];
__device__ float g_p2 [(size_t)Bv*Tv*31*31*8];
__device__ float g_hs3[(size_t)Bv*Tv*29*29*12];
__device__ float g_c3 [(size_t)Bv*29*29*12];
__device__ float g_p3 [(size_t)Bv*Tv*15*15*12];
__device__ float g_hs4[(size_t)Bv*Tv*13*13*16];
__device__ float g_c4 [(size_t)Bv*13*13*16];
__device__ float g_p4 [(size_t)Bv*Tv*7*7*16];
__device__ float g_logits[Bv*50];

__device__ __forceinline__ float hsig(float x) { return __saturatef(0.2f * x + 0.5f); }

template<int FT>
__device__ __forceinline__ void fma_group(float* acc, float v, const float* w) {
    if constexpr (FT == 4) {
        #pragma unroll
        for (int g = 0; g < 4; g++) {
            float4 q = *reinterpret_cast<const float4*>(w + g * 4);
            acc[g*4+0] += v * q.x;
            acc[g*4+1] += v * q.y;
            acc[g*4+2] += v * q.z;
            acc[g*4+3] += v * q.w;
        }
    } else if constexpr (FT == 2) {
        #pragma unroll
        for (int g = 0; g < 4; g++) {
            float2 q = *reinterpret_cast<const float2*>(w + g * 2);
            acc[g*2+0] += v * q.x;
            acc[g*2+1] += v * q.y;
        }
    } else {
        #pragma unroll
        for (int k = 0; k < 4*FT; k++) acc[k] += v * w[k];
    }
}

// One ConvLSTM timestep, fused input conv (VALID) + recurrent conv (SAME) + gates.
// Thread = one output pixel for FT feature channels (all 4 gates).
// grid.y selects the feature-channel group (warp-uniform weight addresses).
template<int CIN, int F, int FT, int HIN, int WIN>
__global__ void lstm_step(const float* __restrict__ in_seq,   // (B,T,HIN,WIN,CIN)
                          const float* __restrict__ Wx,       // (3,3,CIN,4F)
                          const float* __restrict__ Wh,       // (3,3,F,4F)
                          const float* __restrict__ bias,     // (4F,)
                          float* __restrict__ hs,             // (B,T,HO,WO,F)
                          float* __restrict__ c_buf,          // (B,HO,WO,F)
                          int t)
{
    constexpr int HO = HIN - 2, WO = WIN - 2;
    constexpr int C4 = 4 * F;
    constexpr int G4 = 4 * FT;
    constexpr int WXs = 9 * CIN * G4;
    constexpr int WHs = 9 * F * G4;
    __shared__ __align__(16) float sw[WXs + WHs];

    const int f0 = blockIdx.y * FT;

    // Load gate-column-sliced weights into shared.
    for (int i = threadIdx.x; i < WXs; i += blockDim.x) {
        int col = i % G4, rc = i / G4;       // rc = (ky*3+kx)*CIN + ci
        int g = col / FT, j = col % FT;
        sw[i] = Wx[rc * C4 + g * F + f0 + j];
    }
    for (int i = threadIdx.x; i < WHs; i += blockDim.x) {
        int col = i % G4, rc = i / G4;       // rc = (ky*3+kx)*F + ci
        int g = col / FT, j = col % FT;
        sw[WXs + i] = Wh[rc * C4 + g * F + f0 + j];
    }
    __syncthreads();

    const int NPX = Bv * HO * WO;
    int tid = blockIdx.x * blockDim.x + threadIdx.x;
    if (tid >= NPX) return;
    int b = tid / (HO * WO);
    int p = tid % (HO * WO);
    int y = p / WO, x = p % WO;

    float acc[G4];
    #pragma unroll
    for (int g = 0; g < 4; g++)
        #pragma unroll
        for (int j = 0; j < FT; j++)
            acc[g * FT + j] = __ldg(&bias[g * F + f0 + j]);

    // Input conv (VALID, cross-correlation)
    const float* xin = in_seq + ((size_t)(b * Tv + t)) * HIN * WIN * CIN;
    #pragma unroll
    for (int ky = 0; ky < 3; ky++) {
        #pragma unroll
        for (int kx = 0; kx < 3; kx++) {
            const float* px = xin + ((size_t)(y + ky) * WIN + (x + kx)) * CIN;
            const float* wr = sw + (ky * 3 + kx) * CIN * G4;
            #pragma unroll
            for (int ci = 0; ci < CIN; ci++) {
                float v = __ldg(px + ci);
                fma_group<FT>(acc, v, wr + ci * G4);
            }
        }
    }

    // Recurrent conv (SAME, zero pad), h_{t-1} read from hs slice t-1
    if (t > 0) {
        const float* hp = hs + ((size_t)(b * Tv + (t - 1))) * HO * WO * F;
        #pragma unroll
        for (int ky = 0; ky < 3; ky++) {
            int yy = y + ky - 1;
            if (yy < 0 || yy >= HO) continue;
            #pragma unroll
            for (int kx = 0; kx < 3; kx++) {
                int xx = x + kx - 1;
                if (xx < 0 || xx >= WO) continue;
                const float* hv = hp + ((size_t)yy * WO + xx) * F;
                const float* wr = sw + WXs + (ky * 3 + kx) * F * G4;
                #pragma unroll
                for (int ci = 0; ci < F; ci++) {
                    float v = __ldg(hv + ci);
                    fma_group<FT>(acc, v, wr + ci * G4);
                }
            }
        }
    }

    // Gates: order i, f, c, o along channels.
    float* cp = c_buf + (size_t)tid * F + f0;
    float* ho = hs + ((size_t)(b * Tv + t)) * HO * WO * F + (size_t)p * F + f0;
    #pragma unroll
    for (int j = 0; j < FT; j++) {
        float iv = acc[j];
        float fv = acc[FT + j];
        float cv = acc[2 * FT + j];
        float ov = acc[3 * FT + j];
        float cold = (t > 0) ? cp[j] : 0.0f;
        float cn = hsig(fv) * cold + hsig(iv) * tanhf(cv);
        cp[j] = cn;
        ho[j] = hsig(ov) * tanhf(cn);
    }
}

// MaxPool (1,2,2) stride (1,2,2), padding SAME, over (B*T, H, W, C)
__global__ void maxpool_k(const float* __restrict__ in, float* __restrict__ out,
                          int H, int W, int C, int HO, int WO, int total)
{
    int idx = blockIdx.x * blockDim.x + threadIdx.x;
    if (idx >= total) return;
    int c = idx % C; int r = idx / C;
    int ox = r % WO; r /= WO;
    int oy = r % HO; r /= HO;                 // r = bt
    const float* base = in + (size_t)r * H * W * C;
    int iy = 2 * oy, ix = 2 * ox;
    float m = base[((size_t)iy * W + ix) * C + c];
    if (ix + 1 < W) m = fmaxf(m, base[((size_t)iy * W + ix + 1) * C + c]);
    if (iy + 1 < H) {
        m = fmaxf(m, base[((size_t)(iy + 1) * W + ix) * C + c]);
        if (ix + 1 < W) m = fmaxf(m, base[((size_t)(iy + 1) * W + ix + 1) * C + c]);
    }
    out[idx] = m;
}

// Dense: logits[b,k] = sum_j xf[b,j]*Wd[j,k] + bd[k];   FLAT=18816, NC=50
__global__ void dense_k(const float* __restrict__ xf, const float* __restrict__ Wd,
                        const float* __restrict__ bd, float* __restrict__ logits)
{
    const int FLAT = 18816, NC = 50;
    int b = blockIdx.x, k = blockIdx.y;
    float s = 0.0f;
    for (int j = threadIdx.x; j < FLAT; j += blockDim.x)
        s += xf[(size_t)b * FLAT + j] * __ldg(&Wd[(size_t)j * NC + k]);
    __shared__ float red[128];
    red[threadIdx.x] = s;
    __syncthreads();
    for (int off = 64; off > 0; off >>= 1) {
        if (threadIdx.x < off) red[threadIdx.x] += red[threadIdx.x + off];
        __syncthreads();
    }
    if (threadIdx.x == 0) logits[b * NC + k] = red[0] + __ldg(&bd[k]);
}

__global__ void softmax_k(const float* __restrict__ logits, float* __restrict__ out)
{
    const int NC = 50;
    int b = blockIdx.x, t = threadIdx.x;
    __shared__ float s[64];
    float v = (t < NC) ? logits[b * NC + t] : -INFINITY;
    s[t] = v; __syncthreads();
    for (int off = 32; off > 0; off >>= 1) {
        if (t < off) s[t] = fmaxf(s[t], s[t + off]);
        __syncthreads();
    }
    float m = s[0]; __syncthreads();
    float e = (t < NC) ? expf(v - m) : 0.0f;
    s[t] = e; __syncthreads();
    for (int off = 32; off > 0; off >>= 1) {
        if (t < off) s[t] += s[t + off];
        __syncthreads();
    }
    float sum = s[0];
    if (t < NC) out[b * NC + t] = e / sum;
}

template <typename Sym>
static float* symaddr(const Sym& s) {
    void* p = nullptr;
    cudaGetSymbolAddress(&p, s);
    return (float*)p;
}

extern "C" void kernel_launch(void* const* d_in, const int* in_sizes, int n_in,
                              void* d_out, int out_size)
{
    const float* x   = (const float*)d_in[0];
    const float* Wx1 = (const float*)d_in[1];
    const float* Wh1 = (const float*)d_in[2];
    const float* b1  = (const float*)d_in[3];
    const float* Wx2 = (const float*)d_in[4];
    const float* Wh2 = (const float*)d_in[5];
    const float* b2  = (const float*)d_in[6];
    const float* Wx3 = (const float*)d_in[7];
    const float* Wh3 = (const float*)d_in[8];
    const float* b3  = (const float*)d_in[9];
    const float* Wx4 = (const float*)d_in[10];
    const float* Wh4 = (const float*)d_in[11];
    const float* b4  = (const float*)d_in[12];
    const float* Wd  = (const float*)d_in[13];
    const float* bd  = (const float*)d_in[14];
    float* out = (float*)d_out;

    float* hs1 = symaddr(g_hs1); float* c1 = symaddr(g_c1); float* p1 = symaddr(g_p1);
    float* hs2 = symaddr(g_hs2); float* c2 = symaddr(g_c2); float* p2 = symaddr(g_p2);
    float* hs3 = symaddr(g_hs3); float* c3 = symaddr(g_c3); float* p3 = symaddr(g_p3);
    float* hs4 = symaddr(g_hs4); float* c4 = symaddr(g_c4); float* p4 = symaddr(g_p4);
    float* logits = symaddr(g_logits);

    const int TB = 256;

    // ---- Layer 1: CIN=3, F=4, FT=4 (NG=1), 128x128 -> 126x126 ----
    {
        int npx = Bv * 126 * 126;
        dim3 grid((npx + TB - 1) / TB, 1);
        for (int t = 0; t < Tv; t++)
            lstm_step<3, 4, 4, 128, 128><<<grid, TB>>>(x, Wx1, Wh1, b1, hs1, c1, t);
        int total = Bv * Tv * 63 * 63 * 4;
        maxpool_k<<<(total + TB - 1) / TB, TB>>>(hs1, p1, 126, 126, 4, 63, 63, total);
    }
    // ---- Layer 2: CIN=4, F=8, FT=4 (NG=2), 63x63 -> 61x61 ----
    {
        int npx = Bv * 61 * 61;
        dim3 grid((npx + TB - 1) / TB, 2);
        for (int t = 0; t < Tv; t++)
            lstm_step<4, 8, 4, 63, 63><<<grid, TB>>>(p1, Wx2, Wh2, b2, hs2, c2, t);
        int total = Bv * Tv * 31 * 31 * 8;
        maxpool_k<<<(total + TB - 1) / TB, TB>>>(hs2, p2, 61, 61, 8, 31, 31, total);
    }
    // ---- Layer 3: CIN=8, F=12, FT=4 (NG=3), 31x31 -> 29x29 ----
    {
        int npx = Bv * 29 * 29;
        dim3 grid((npx + TB - 1) / TB, 3);
        for (int t = 0; t < Tv; t++)
            lstm_step<8, 12, 4, 31, 31><<<grid, TB>>>(p2, Wx3, Wh3, b3, hs3, c3, t);
        int total = Bv * Tv * 15 * 15 * 12;
        maxpool_k<<<(total + TB - 1) / TB, TB>>>(hs3, p3, 29, 29, 12, 15, 15, total);
    }
    // ---- Layer 4: CIN=12, F=16, FT=2 (NG=8), 15x15 -> 13x13 ----
    {
        int npx = Bv * 13 * 13;
        dim3 grid((npx + TB - 1) / TB, 8);
        for (int t = 0; t < Tv; t++)
            lstm_step<12, 16, 2, 15, 15><<<grid, TB>>>(p3, Wx4, Wh4, b4, hs4, c4, t);
        int total = Bv * Tv * 7 * 7 * 16;
        maxpool_k<<<(total + TB - 1) / TB, TB>>>(hs4, p4, 13, 13, 16, 7, 7, total);
    }

    // ---- Dense + softmax ----
    dim3 dgrid(Bv, 50);
    dense_k<<<dgrid, 128>>>(p4, Wd, bd, logits);
    softmax_k<<<Bv, 64>>>(logits, out);
}